// round 11
// baseline (speedup 1.0000x reference)
#include <cuda_runtime.h>
#include <math.h>

#define TILE_W 16
#define TILE_H 8
#define SUP_W 64
#define SUP_H 64
#define MAX_G 2048
#define MAX_SUP 256
#define MAH_CUT 37.0f        // density threshold ~ exp(-18.5)
#define LOG2E 1.4426950408889634f

// ---- stage 1: depth-sorted packed gaussians ----
__device__ float4 g_pA[MAX_G];   // mx, my, cullR^2, a' (= -0.5*iA*log2e)
__device__ float4 g_pB[MAX_G];   // b' (= -iB*log2e), c' (= -0.5*iC*log2e), log2(opac), colR
__device__ float2 g_pC[MAX_G];   // colG, colB

// ---- stage 2: per-supertile depth-ordered MATERIALIZED lists (L2-resident) ----
__device__ float4 t_A[MAX_SUP * MAX_G];  // mx, my, a', b'
__device__ float4 t_B[MAX_SUP * MAX_G];  // c', log2(opac), colR, colG
__device__ float  t_C[MAX_SUP * MAX_G];  // colB
__device__ int    s_cnt[MAX_SUP];

__device__ __forceinline__ float ex2(float x) {
    float r;
    asm("ex2.approx.ftz.f32 %0, %1;" : "=f"(r) : "f"(x));
    return r;
}

// ---- 1) prep: warp-per-gaussian stable rank + preprocess + scatter ----
__global__ void __launch_bounds__(256) prep_kernel(
        const float* __restrict__ means,
        const float* __restrict__ log_scale,
        const float* __restrict__ rot,
        const float* __restrict__ colour_logits,
        const float* __restrict__ opacity_logit,
        const float* __restrict__ depth,
        int G) {
    __shared__ float sd[MAX_G];
    for (int j = threadIdx.x; j < G; j += blockDim.x) sd[j] = depth[j];
    __syncthreads();

    int w    = threadIdx.x >> 5;
    int lane = threadIdx.x & 31;
    int i = blockIdx.x * 8 + w;
    if (i >= G) return;

    float di = sd[i];
    int r = 0;
    for (int j = lane; j < G; j += 32) {
        float dj = sd[j];
        r += (dj < di) || (dj == di && j < i);
    }
    r = __reduce_add_sync(0xffffffffu, r);

    if (lane == 0) {
        float s2x = __expf(2.f * log_scale[2 * i + 0]);
        float s2y = __expf(2.f * log_scale[2 * i + 1]);
        float s, c;
        __sincosf(rot[i], &s, &c);

        float ca = c * c * s2x + s * s * s2y;
        float cb = c * s * (s2x - s2y);
        float cd = s * s * s2x + c * c * s2y;
        float det = ca * cd - cb * cb;
        float inv = 1.f / det;
        float iA = cd * inv;
        float iB = -cb * inv;
        float iC = ca * inv;

        float opac = 1.f / (1.f + __expf(-opacity_logit[i]));
        float cr  = 1.f / (1.f + __expf(-colour_logits[3 * i + 0]));
        float cg  = 1.f / (1.f + __expf(-colour_logits[3 * i + 1]));
        float cbl = 1.f / (1.f + __expf(-colour_logits[3 * i + 2]));

        float tr = 0.5f * (ca + cd);
        float lmax = tr + sqrtf(fmaxf(tr * tr - det, 0.f));

        g_pA[r] = make_float4(means[2 * i + 0], means[2 * i + 1],
                              MAH_CUT * lmax, -0.5f * iA * LOG2E);
        g_pB[r] = make_float4(-iB * LOG2E, -0.5f * iC * LOG2E,
                              __log2f(opac), cr);
        g_pC[r] = make_float2(cg, cbl);
    }
}

// ---- 2) supertile binning: block (256thr) per 64x64 supertile ----
// Writes depth-ordered, fully-materialized per-supertile gaussian data.
__global__ void __launch_bounds__(256) sbin_kernel(int G, int nsx) {
    int st = blockIdx.x;
    float x0 = (float)((st % nsx) * SUP_W);
    float y0 = (float)((st / nsx) * SUP_H);
    float x1 = x0 + (float)(SUP_W - 1);
    float y1 = y0 + (float)(SUP_H - 1);

    int wid  = threadIdx.x >> 5;
    int lane = threadIdx.x & 31;
    unsigned lmask = (1u << lane) - 1u;
    size_t tbase = (size_t)st * MAX_G;

    __shared__ int swcnt[8];

    int cnt = 0;
    for (int base = 0; base < G; base += 256) {
        int g = base + threadIdx.x;
        bool hit = false;
        float4 A;
        if (g < G) {
            A = g_pA[g];
            float ddx = fmaxf(fmaxf(x0 - A.x, A.x - x1), 0.f);
            float ddy = fmaxf(fmaxf(y0 - A.y, A.y - y1), 0.f);
            hit = (ddx * ddx + ddy * ddy) <= A.z;
        }
        // early predicated loads overlap ballot/prefix latency
        float4 B;
        float2 C;
        if (hit) {
            B = g_pB[g];
            C = g_pC[g];
        }
        unsigned m = __ballot_sync(0xffffffffu, hit);
        if (lane == 0) swcnt[wid] = __popc(m);
        __syncthreads();
        int woff = 0, total = 0;
#pragma unroll
        for (int w = 0; w < 8; w++) {
            int cw = swcnt[w];
            woff += (w < wid) ? cw : 0;
            total += cw;
        }
        if (hit) {
            int idx = cnt + woff + __popc(m & lmask);
            t_A[tbase + idx] = make_float4(A.x, A.y, A.w, B.x);  // mx,my,a',b'
            t_B[tbase + idx] = make_float4(B.y, B.z, B.w, C.x);  // c',lop,cr,cg
            t_C[tbase + idx] = C.y;                              // cb
        }
        cnt += total;
        __syncthreads();
    }
    if (threadIdx.x == 0) s_cnt[st] = cnt;
}

// ---- 3) raster: block per 16x8 tile; pure composite, no barriers/ballots ----
__global__ void __launch_bounds__(128) raster_kernel(int W, int H, int ntx, int nsx,
                                                     float* __restrict__ out) {
    int tile = blockIdx.x;
    int tx = tile % ntx, ty = tile / ntx;
    int lx = threadIdx.x & (TILE_W - 1);
    int ly = threadIdx.x >> 4;
    int px = tx * TILE_W + lx;
    int py = ty * TILE_H + ly;
    float fx = (float)px, fy = (float)py;

    int st = (ty >> 3) * nsx + (tx >> 2);   // 4x8 tiles per 64x64 supertile
    int n = s_cnt[st];
    size_t tbase = (size_t)st * MAX_G;
    const float4* __restrict__ pA = t_A + tbase;
    const float4* __restrict__ pB = t_B + tbase;
    const float*  __restrict__ pC = t_C + tbase;

    float T = 1.f, accR = 0.f, accG = 0.f, accB = 0.f;

#pragma unroll 4
    for (int j = 0; j < n; j++) {
        float4 Aj = __ldg(pA + j);   // block-uniform -> L1 broadcast
        float4 Bj = __ldg(pB + j);
        float  Cj = __ldg(pC + j);
        float dx = fx - Aj.x;
        float dy = fy - Aj.y;
        float e = fmaf(Aj.z, dx * dx,
                  fmaf(Aj.w, dx * dy,
                  fmaf(Bj.x, dy * dy, Bj.y)));
        float alpha = fminf(ex2(e), 0.99f);   // non-overlapping candidates -> ex2 underflows to 0
        float wgt = T * alpha;
        accR = fmaf(wgt, Bj.z, accR);
        accG = fmaf(wgt, Bj.w, accG);
        accB = fmaf(wgt, Cj, accB);
        T = T - wgt;
    }

    if (px < W && py < H) {
        int o = (py * W + px) * 3;
        out[o + 0] = accR;
        out[o + 1] = accG;
        out[o + 2] = accB;
    }
}

extern "C" void kernel_launch(void* const* d_in, const int* in_sizes, int n_in,
                              void* d_out, int out_size) {
    const float* means         = (const float*)d_in[0];
    const float* log_scale     = (const float*)d_in[1];
    const float* rot           = (const float*)d_in[2];
    const float* colour_logits = (const float*)d_in[3];
    const float* opacity_logit = (const float*)d_in[4];
    const float* depth         = (const float*)d_in[5];

    int G = in_sizes[5];
    if (G > MAX_G) G = MAX_G;

    int HW = out_size / 3;
    int W = (int)(sqrt((double)HW) + 0.5);
    if (W <= 0) W = 1;
    int H = HW / W;

    int ntx = (W + TILE_W - 1) / TILE_W;
    int nty = (H + TILE_H - 1) / TILE_H;
    int ntiles = ntx * nty;

    int nsx = (ntx + 3) / 4;   // 64 px per supertile in x
    int nsy = (nty + 7) / 8;   // 64 px per supertile in y
    int nsup = nsx * nsy;
    if (nsup > MAX_SUP) nsup = MAX_SUP;

    prep_kernel<<<(G + 7) / 8, 256>>>(means, log_scale, rot,
                                      colour_logits, opacity_logit, depth, G);
    sbin_kernel<<<nsup, 256>>>(G, nsx);
    raster_kernel<<<ntiles, 128>>>(W, H, ntx, nsx, (float*)d_out);
}

// round 12
// speedup vs baseline: 1.9899x; 1.9899x over previous
#include <cuda_runtime.h>
#include <math.h>

#define TILE 16              // 16x16 pixel tile per block
#define NTHREADS 128         // 2 pixels per thread (ly and ly+8)
#define NW 4
#define MAX_G 2048
#define CHUNK 512
#define RPW (CHUNK / NW)     // 128 gaussians per warp per chunk
#define ROUNDS (RPW / 32)    // 4 ballot rounds
#define MAH_CUT 37.0f
#define LOG2E 1.4426950408889634f

// ---- depth-sorted packed gaussians ----
__device__ float4 g_pA[MAX_G];   // mx, my, cullR^2, a' (= -0.5*iA*log2e)
__device__ float4 g_pB[MAX_G];   // b' (= -iB*log2e), c' (= -0.5*iC*log2e), log2(opac), colR
__device__ float2 g_pC[MAX_G];   // colG, colB

// ---- software grid barrier (replay-safe: generation is monotonic) ----
__device__ unsigned g_bar_count = 0;
__device__ volatile unsigned g_bar_gen = 0;

__device__ __forceinline__ void grid_barrier(unsigned nblocks) {
    __syncthreads();
    if (threadIdx.x == 0) {
        unsigned gen = g_bar_gen;
        __threadfence();
        unsigned old = atomicAdd(&g_bar_count, 1u);
        if (old == nblocks - 1u) {
            g_bar_count = 0;
            __threadfence();
            g_bar_gen = gen + 1u;
        } else {
            while (g_bar_gen == gen) __nanosleep(64);
        }
        __threadfence();
    }
    __syncthreads();
}

__device__ __forceinline__ float ex2(float x) {
    float r;
    asm("ex2.approx.ftz.f32 %0, %1;" : "=f"(r) : "f"(x));
    return r;
}

__global__ void __launch_bounds__(NTHREADS, 8) fused_kernel(
        const float* __restrict__ means,
        const float* __restrict__ log_scale,
        const float* __restrict__ rot,
        const float* __restrict__ colour_logits,
        const float* __restrict__ opacity_logit,
        const float* __restrict__ depth,
        int G, int W, int H, int ntx, int ntiles,
        float* __restrict__ out) {
    int wid  = threadIdx.x >> 5;
    int lane = threadIdx.x & 31;

    // ================= Phase A: prep (blocks 0..255, warp per gaussian) ====
    if (blockIdx.x < 256) {
        for (int i = blockIdx.x * 4 + wid; i < G; i += 1024) {
            float di = depth[i];
            int r = 0;
            for (int j = lane; j < G; j += 32) {
                float dj = depth[j];
                r += (dj < di) || (dj == di && j < i);
            }
            r = __reduce_add_sync(0xffffffffu, r);

            if (lane == 0) {
                float s2x = __expf(2.f * log_scale[2 * i + 0]);
                float s2y = __expf(2.f * log_scale[2 * i + 1]);
                float s, c;
                __sincosf(rot[i], &s, &c);

                float ca = c * c * s2x + s * s * s2y;
                float cb = c * s * (s2x - s2y);
                float cd = s * s * s2x + c * c * s2y;
                float det = ca * cd - cb * cb;
                float inv = 1.f / det;
                float iA = cd * inv;
                float iB = -cb * inv;
                float iC = ca * inv;

                float opac = 1.f / (1.f + __expf(-opacity_logit[i]));
                float cr  = 1.f / (1.f + __expf(-colour_logits[3 * i + 0]));
                float cg  = 1.f / (1.f + __expf(-colour_logits[3 * i + 1]));
                float cbl = 1.f / (1.f + __expf(-colour_logits[3 * i + 2]));

                float tr = 0.5f * (ca + cd);
                float lmax = tr + sqrtf(fmaxf(tr * tr - det, 0.f));

                g_pA[r] = make_float4(means[2 * i + 0], means[2 * i + 1],
                                      MAH_CUT * lmax, -0.5f * iA * LOG2E);
                g_pB[r] = make_float4(-iB * LOG2E, -0.5f * iC * LOG2E,
                                      __log2f(opac), cr);
                g_pC[r] = make_float2(cg, cbl);
            }
        }
    }

    grid_barrier(gridDim.x);

    // ================= Phase C: raster (block per 16x16 tile, 2 px/thread) =
    if (blockIdx.x >= (unsigned)ntiles) return;

    int tile = blockIdx.x;
    int tx = tile % ntx, ty = tile / ntx;
    int lx = threadIdx.x & (TILE - 1);
    int ly = threadIdx.x >> 4;            // 0..7 -> rows ly and ly+8
    int px = tx * TILE + lx;
    int py = ty * TILE + ly;
    float fx = (float)px, fy = (float)py;

    float x0 = (float)(tx * TILE);
    float y0 = (float)(ty * TILE);
    float x1 = x0 + (float)(TILE - 1);
    float y1 = y0 + (float)(TILE - 1);

    unsigned lmask = (1u << lane) - 1u;

    __shared__ float4 sA[CHUNK];
    __shared__ float4 sB[CHUNK];
    __shared__ float  sC[CHUNK];
    __shared__ int    scnt[NW];

    float T1 = 1.f, r1 = 0.f, g1 = 0.f, b1 = 0.f;
    float T2 = 1.f, r2c = 0.f, g2c = 0.f, b2c = 0.f;

    for (int c0 = 0; c0 < G; c0 += CHUNK) {
        int gw = c0 + wid * RPW;

        // prefetch cull data (one LDG.128 per gaussian, independent)
        float4 Ar[ROUNDS];
#pragma unroll
        for (int r = 0; r < ROUNDS; r++) {
            int g = gw + r * 32 + lane;
            Ar[r] = (g < G) ? g_pA[g] : make_float4(1e30f, 1e30f, -1.f, 0.f);
        }

        bool hr[ROUNDS];
#pragma unroll
        for (int r = 0; r < ROUNDS; r++) {
            float ddx = fmaxf(fmaxf(x0 - Ar[r].x, Ar[r].x - x1), 0.f);
            float ddy = fmaxf(fmaxf(y0 - Ar[r].y, Ar[r].y - y1), 0.f);
            hr[r] = (ddx * ddx + ddy * ddy) <= Ar[r].z;
        }

        unsigned mask[ROUNDS];
        int offr[ROUNDS];
        int cnt = 0;
#pragma unroll
        for (int r = 0; r < ROUNDS; r++) {
            mask[r] = __ballot_sync(0xffffffffu, hr[r]);
            offr[r] = cnt;
            cnt += __popc(mask[r]);
        }
        if (lane == 0) scnt[wid] = cnt;
        __syncthreads();   // also guards prev-chunk composite reads

        int woff = 0, total = 0;
#pragma unroll
        for (int w = 0; w < NW; w++) {
            int cw = scnt[w];
            woff += (w < wid) ? cw : 0;
            total += cw;
        }

#pragma unroll
        for (int r = 0; r < ROUNDS; r++) {
            if (hr[r]) {
                int g = gw + r * 32 + lane;
                float4 B = g_pB[g];
                float2 C = g_pC[g];
                int idx = woff + offr[r] + __popc(mask[r] & lmask);
                sA[idx] = make_float4(Ar[r].x, Ar[r].y, Ar[r].w, B.x); // mx,my,a',b'
                sB[idx] = make_float4(B.y, B.z, B.w, C.x);             // c',lop,cr,cg
                sC[idx] = C.y;                                          // cb
            }
        }
        __syncthreads();

        // composite 2 pixels per thread, flat branch-free loop
#pragma unroll 4
        for (int j = 0; j < total; j++) {
            float4 Aj = sA[j];
            float4 Bj = sB[j];
            float  Cj = sC[j];
            float dx  = fx - Aj.x;
            float dy  = fy - Aj.y;
            float dy2 = dy + 8.f;
            float t0 = fmaf(Aj.z, dx * dx, Bj.y);          // a'*dx^2 + lop
            float e1 = fmaf(Aj.w, dx * dy,  fmaf(Bj.x, dy  * dy,  t0));
            float e2 = fmaf(Aj.w, dx * dy2, fmaf(Bj.x, dy2 * dy2, t0));
            float a1 = fminf(ex2(e1), 0.99f);
            float a2 = fminf(ex2(e2), 0.99f);
            float w1 = T1 * a1;
            float w2 = T2 * a2;
            r1  = fmaf(w1, Bj.z, r1);   g1  = fmaf(w1, Bj.w, g1);   b1  = fmaf(w1, Cj, b1);
            r2c = fmaf(w2, Bj.z, r2c);  g2c = fmaf(w2, Bj.w, g2c);  b2c = fmaf(w2, Cj, b2c);
            T1 -= w1;
            T2 -= w2;
        }
    }

    if (px < W) {
        if (py < H) {
            int o = (py * W + px) * 3;
            out[o + 0] = r1; out[o + 1] = g1; out[o + 2] = b1;
        }
        if (py + 8 < H) {
            int o = ((py + 8) * W + px) * 3;
            out[o + 0] = r2c; out[o + 1] = g2c; out[o + 2] = b2c;
        }
    }
}

extern "C" void kernel_launch(void* const* d_in, const int* in_sizes, int n_in,
                              void* d_out, int out_size) {
    const float* means         = (const float*)d_in[0];
    const float* log_scale     = (const float*)d_in[1];
    const float* rot           = (const float*)d_in[2];
    const float* colour_logits = (const float*)d_in[3];
    const float* opacity_logit = (const float*)d_in[4];
    const float* depth         = (const float*)d_in[5];

    int G = in_sizes[5];
    if (G > MAX_G) G = MAX_G;

    int HW = out_size / 3;
    int W = (int)(sqrt((double)HW) + 0.5);
    if (W <= 0) W = 1;
    int H = HW / W;

    int ntx = (W + TILE - 1) / TILE;
    int nty = (H + TILE - 1) / TILE;
    int ntiles = ntx * nty;

    int nblocks = ntiles > 256 ? ntiles : 256;   // must cover prep blocks too
    fused_kernel<<<nblocks, NTHREADS>>>(means, log_scale, rot, colour_logits,
                                        opacity_logit, depth,
                                        G, W, H, ntx, ntiles, (float*)d_out);
}